// round 12
// baseline (speedup 1.0000x reference)
#include <cuda_runtime.h>
#include <cuda_fp16.h>
#include <cstdint>

// ---------------------------------------------------------------------------
// Problem constants
// ---------------------------------------------------------------------------
#define M_DIM 256
#define K_DIM 4096
#define N_DIM 11008
#define G_DIM 32
#define R_DIM 16
#define SCALING 2.0f

#define BM 64
#define BN 64
#define BK 32
#define KT (K_DIM / BK)     // 128

// SMEM: 4 stages. A [64][32] fp16 pitch 80 (5120 B), B [64][32] fp16 pitch 80.
#define PITCH  80
#define A_ST   5120
#define NSTG   4
#define B_BASE (NSTG * A_ST)              // 20480
#define B_ST   5120
#define SMEM_BYTES (B_BASE + NSTG * B_ST) // 40960  -> 5 CTAs/SM
// LoRA tiles reuse stage-0 smem after the main loop:
#define SXA 0        // xa [64][16] fp16, pitch 32
#define SLB 2048     // lB [64][16] fp16, pitch 32

// Global scratch
__device__ __align__(16) float  g_xa[M_DIM * R_DIM];
__device__ __align__(16) __half g_x16[(size_t)M_DIM * K_DIM];   // x in fp16
__device__ __align__(16) __half g_w16[(size_t)N_DIM * K_DIM];   // (q-z)*s in fp16

// ---------------------------------------------------------------------------
// helpers (family-common PTX)
// ---------------------------------------------------------------------------
__device__ __forceinline__ uint32_t smem_u32(const void* p) {
    uint32_t a;
    asm("{ .reg .u64 t; cvta.to.shared.u64 t, %1; cvt.u32.u64 %0, t; }"
        : "=r"(a) : "l"(p));
    return a;
}
__device__ __forceinline__ void ldsm_x4(uint32_t addr, uint32_t* r) {
    asm volatile("ldmatrix.sync.aligned.m8n8.x4.shared.b16 {%0,%1,%2,%3}, [%4];"
                 : "=r"(r[0]), "=r"(r[1]), "=r"(r[2]), "=r"(r[3]) : "r"(addr));
}
__device__ __forceinline__ void mma_f16(float* c, const uint32_t* a, const uint32_t* b) {
    asm volatile(
        "mma.sync.aligned.m16n8k16.row.col.f32.f16.f16.f32 "
        "{%0,%1,%2,%3}, {%4,%5,%6,%7}, {%8,%9}, {%0,%1,%2,%3};"
        : "+f"(c[0]), "+f"(c[1]), "+f"(c[2]), "+f"(c[3])
        : "r"(a[0]), "r"(a[1]), "r"(a[2]), "r"(a[3]), "r"(b[0]), "r"(b[1]));
}
__device__ __forceinline__ void cpa16(uint32_t dst, const void* src) {
    asm volatile("cp.async.cg.shared.global [%0], [%1], 16;"
                 :: "r"(dst), "l"(src) : "memory");
}
__device__ __forceinline__ void cpa_commit() {
    asm volatile("cp.async.commit_group;" ::: "memory");
}
__device__ __forceinline__ void cpa_wait2() {
    asm volatile("cp.async.wait_group 2;" ::: "memory");
}
__device__ __forceinline__ uint32_t pack_f16(float v0, float v1) {
    __half2 p = __floats2half2_rn(v0, v1);
    return *reinterpret_cast<uint32_t*>(&p);
}

// ---------------------------------------------------------------------------
// Kernel 0a: x -> fp16
// ---------------------------------------------------------------------------
__global__ __launch_bounds__(256)
void x16_kernel(const float* __restrict__ x) {
    const size_t i8 = ((size_t)blockIdx.x * 256 + threadIdx.x) * 8;
    float4 v0 = reinterpret_cast<const float4*>(x + i8)[0];
    float4 v1 = reinterpret_cast<const float4*>(x + i8)[1];
    uint4 o;
    o.x = pack_f16(v0.x, v0.y);
    o.y = pack_f16(v0.z, v0.w);
    o.z = pack_f16(v1.x, v1.y);
    o.w = pack_f16(v1.z, v1.w);
    *reinterpret_cast<uint4*>(g_x16 + i8) = o;
}

// ---------------------------------------------------------------------------
// Kernel 0b: w16 = (qweight - zeros) * scales in fp16 (scale folded in)
// ---------------------------------------------------------------------------
__global__ __launch_bounds__(256)
void pack_w16(const int* __restrict__ qw, const int* __restrict__ zeros,
              const float* __restrict__ scales) {
    const size_t base = ((size_t)blockIdx.x * 256 + threadIdx.x) * 8;
    const int o = (int)(base >> 12);
    const int i = (int)(base & 4095);
    const int g = o * G_DIM + (i >> 7);
    const float z = (float)zeros[g];
    const float s = scales[g];
    const float nz = -z * s;
    int4 a = reinterpret_cast<const int4*>(qw + base)[0];
    int4 b = reinterpret_cast<const int4*>(qw + base)[1];
    uint4 w;
    w.x = pack_f16(fmaf((float)a.x, s, nz), fmaf((float)a.y, s, nz));
    w.y = pack_f16(fmaf((float)a.z, s, nz), fmaf((float)a.w, s, nz));
    w.z = pack_f16(fmaf((float)b.x, s, nz), fmaf((float)b.y, s, nz));
    w.w = pack_f16(fmaf((float)b.z, s, nz), fmaf((float)b.w, s, nz));
    *reinterpret_cast<uint4*>(g_w16 + base) = w;
}

// ---------------------------------------------------------------------------
// Kernel 1: xa[m, r] = SCALING * sum_k x[m,k] * lora_A[r,k]
// ---------------------------------------------------------------------------
__global__ __launch_bounds__(256)
void lora_xa_kernel(const float* __restrict__ x, const float* __restrict__ loraA) {
    const int m   = blockIdx.x;
    const int tid = threadIdx.x;
    const int lid = tid & 31;
    const int wid = tid >> 5;

    float acc[R_DIM];
#pragma unroll
    for (int r = 0; r < R_DIM; r++) acc[r] = 0.f;

    const float4* x4 = reinterpret_cast<const float4*>(x + (size_t)m * K_DIM);
    const float4* a4 = reinterpret_cast<const float4*>(loraA);
#pragma unroll
    for (int i = 0; i < 4; i++) {
        int f = tid + i * 256;
        float4 xv = x4[f];
#pragma unroll
        for (int r = 0; r < R_DIM; r++) {
            float4 av = a4[r * (K_DIM / 4) + f];
            acc[r] = fmaf(xv.x, av.x, acc[r]);
            acc[r] = fmaf(xv.y, av.y, acc[r]);
            acc[r] = fmaf(xv.z, av.z, acc[r]);
            acc[r] = fmaf(xv.w, av.w, acc[r]);
        }
    }
#pragma unroll
    for (int r = 0; r < R_DIM; r++) {
#pragma unroll
        for (int o = 16; o > 0; o >>= 1)
            acc[r] += __shfl_xor_sync(0xFFFFFFFFu, acc[r], o);
    }
    __shared__ float red[8][R_DIM];
    if (lid == 0) {
#pragma unroll
        for (int r = 0; r < R_DIM; r++) red[wid][r] = acc[r];
    }
    __syncthreads();
    if (tid < R_DIM) {
        float v = 0.f;
#pragma unroll
        for (int w = 0; w < 8; w++) v += red[w][tid];
        g_xa[m * R_DIM + tid] = v * SCALING;
    }
}

// ---------------------------------------------------------------------------
// Kernel 2: main GEMM. CTA 64x64, 64 threads, 2 warps (warp tile 32x64),
// BK=32, 4-stage cp.async ring, distance-3 prefetch, 5 CTAs/SM.
// Warp tile 32x64 -> 6 ldsm_x4 per 16 HMMA (0.375/MMA vs 0.5 in R10).
// Scales pre-folded; tac accumulates f32 directly; LoRA k16 epilogue.
// ---------------------------------------------------------------------------
__global__ __launch_bounds__(64, 5)
void gptq_lora_mma(const float* __restrict__ loraB,
                   float*       __restrict__ out) {
    extern __shared__ __align__(16) char sm[];
    const uint32_t sb = smem_u32(sm);

    const int tid  = threadIdx.x;
    const int lane = tid & 31;
    const int wid  = tid >> 5;
    const int m0   = blockIdx.x * BM;    // 4 m-tiles (fastest -> w16 L2 dedup)
    const int n0   = blockIdx.y * BN;    // 172 n-tiles

    // ---- loader mappings: 1 thread/row, 4x16B chunks per tile ----
    const __half* ag = g_x16 + (size_t)(m0 + tid) * K_DIM;
    const __half* bg = g_w16 + (size_t)(n0 + tid) * K_DIM;
    const uint32_t l_soff = (uint32_t)(tid * PITCH);

    // ---- prologue: stages 0..2 ----
#pragma unroll
    for (int s = 0; s < 3; s++) {
        const uint32_t As = sb + s * A_ST + l_soff;
        const uint32_t Bs = sb + B_BASE + s * B_ST + l_soff;
        cpa16(As,      ag + s * BK);
        cpa16(As + 16, ag + s * BK + 8);
        cpa16(As + 32, ag + s * BK + 16);
        cpa16(As + 48, ag + s * BK + 24);
        cpa16(Bs,      bg + s * BK);
        cpa16(Bs + 16, bg + s * BK + 8);
        cpa16(Bs + 32, bg + s * BK + 16);
        cpa16(Bs + 48, bg + s * BK + 24);
        cpa_commit();
    }

    // ---- accumulators / compute mappings ----
    float tac[2][8][4];
#pragma unroll
    for (int mi = 0; mi < 2; mi++)
#pragma unroll
        for (int ni = 0; ni < 8; ni++)
#pragma unroll
            for (int j = 0; j < 4; j++) tac[mi][ni][j] = 0.f;

    const int wm = wid * 32;                    // warp rows: wm..wm+31, full 64 n
    const uint32_t aoff  = (uint32_t)((wm + (lane & 15)) * PITCH + ((lane >> 4) << 4));
    const uint32_t boff4 = (uint32_t)(((lane & 7) + ((lane >> 4) << 3)) * PITCH
                                      + (((lane >> 3) & 1) << 4));

    cpa_wait2();          // stage 0 complete (own groups)
    __syncthreads();      // all threads' -> fully visible

    // frag double buffers
    uint32_t fa[2][2][4], fb[2][8][2];

    for (int kt = 0; kt < KT; kt++) {
        // 1. prefetch stage kt+3 (distance 3)
        if (kt < KT - 3) {
            const int ks = kt + 3;
            const int st = ks & 3;
            const uint32_t As = sb + st * A_ST + l_soff;
            const uint32_t Bs = sb + B_BASE + st * B_ST + l_soff;
            cpa16(As,      ag + ks * BK);
            cpa16(As + 16, ag + ks * BK + 8);
            cpa16(As + 32, ag + ks * BK + 16);
            cpa16(As + 48, ag + ks * BK + 24);
            cpa16(Bs,      bg + ks * BK);
            cpa16(Bs + 16, bg + ks * BK + 8);
            cpa16(Bs + 32, bg + ks * BK + 16);
            cpa16(Bs + 48, bg + ks * BK + 24);
        }
        cpa_commit();

        // 2. compute stage kt&3: 2 x k16, 16 HMMA each, frag-double-buffered
        {
            const uint32_t Ab = sb + (uint32_t)((kt & 3) * A_ST) + aoff;
            const uint32_t Bb = sb + B_BASE + (uint32_t)((kt & 3) * B_ST) + boff4;

            // load kk=0 into buffer 0
#pragma unroll
            for (int mi = 0; mi < 2; mi++)
                ldsm_x4(Ab + mi * (16 * PITCH), fa[0][mi]);
#pragma unroll
            for (int nj = 0; nj < 4; nj++) {
                uint32_t t[4];
                ldsm_x4(Bb + nj * (16 * PITCH), t);
                fb[0][2 * nj][0] = t[0]; fb[0][2 * nj][1] = t[1];
                fb[0][2 * nj + 1][0] = t[2]; fb[0][2 * nj + 1][1] = t[3];
            }
#pragma unroll
            for (int kk = 0; kk < 2; kk++) {
                const int cur = kk & 1, nxt = cur ^ 1;
                if (kk < 1) {
                    const uint32_t kb = 32;   // second k16 half
#pragma unroll
                    for (int mi = 0; mi < 2; mi++)
                        ldsm_x4(Ab + mi * (16 * PITCH) + kb, fa[nxt][mi]);
#pragma unroll
                    for (int nj = 0; nj < 4; nj++) {
                        uint32_t t[4];
                        ldsm_x4(Bb + nj * (16 * PITCH) + kb, t);
                        fb[nxt][2 * nj][0] = t[0]; fb[nxt][2 * nj][1] = t[1];
                        fb[nxt][2 * nj + 1][0] = t[2]; fb[nxt][2 * nj + 1][1] = t[3];
                    }
                }
#pragma unroll
                for (int mi = 0; mi < 2; mi++)
#pragma unroll
                    for (int ni = 0; ni < 8; ni++)
                        mma_f16(tac[mi][ni], fa[cur][mi], fb[cur][ni]);
            }
        }

        // 3. stage kt+1 complete; publish
        cpa_wait2();
        __syncthreads();
    }

    // ---- LoRA tiles: reuse stage-0 smem (all compute done); 2 rows/thread ----
    {
        // xa row tid
        {
            const float* src = g_xa + (size_t)(m0 + tid) * R_DIM;
            char* dst = sm + SXA + tid * 32;
            float4 v0 = reinterpret_cast<const float4*>(src)[0];
            float4 v1 = reinterpret_cast<const float4*>(src)[1];
            float4 v2 = reinterpret_cast<const float4*>(src)[2];
            float4 v3 = reinterpret_cast<const float4*>(src)[3];
            *reinterpret_cast<uint4*>(dst) =
                make_uint4(pack_f16(v0.x, v0.y), pack_f16(v0.z, v0.w),
                           pack_f16(v1.x, v1.y), pack_f16(v1.z, v1.w));
            *reinterpret_cast<uint4*>(dst + 16) =
                make_uint4(pack_f16(v2.x, v2.y), pack_f16(v2.z, v2.w),
                           pack_f16(v3.x, v3.y), pack_f16(v3.z, v3.w));
        }
        // loraB row tid
        {
            const float* src = loraB + (size_t)(n0 + tid) * R_DIM;
            char* dst = sm + SLB + tid * 32;
            float4 v0 = reinterpret_cast<const float4*>(src)[0];
            float4 v1 = reinterpret_cast<const float4*>(src)[1];
            float4 v2 = reinterpret_cast<const float4*>(src)[2];
            float4 v3 = reinterpret_cast<const float4*>(src)[3];
            *reinterpret_cast<uint4*>(dst) =
                make_uint4(pack_f16(v0.x, v0.y), pack_f16(v0.z, v0.w),
                           pack_f16(v1.x, v1.y), pack_f16(v1.z, v1.w));
            *reinterpret_cast<uint4*>(dst + 16) =
                make_uint4(pack_f16(v2.x, v2.y), pack_f16(v2.z, v2.w),
                           pack_f16(v3.x, v3.y), pack_f16(v3.z, v3.w));
        }
    }
    __syncthreads();

    // ---- LoRA k16 step (pitch-32 tiles) ----
    {
        uint32_t ah[2][4], b[8][2];
        const uint32_t aoffL = (uint32_t)((wm + (lane & 15)) * 32 + ((lane >> 4) << 4));
        const uint32_t boffL = (uint32_t)(((lane & 7) + ((lane >> 4) << 3)) * 32
                                          + (((lane >> 3) & 1) << 4));
#pragma unroll
        for (int mi = 0; mi < 2; mi++)
            ldsm_x4(sb + SXA + aoffL + mi * (16 * 32), ah[mi]);
#pragma unroll
        for (int nj = 0; nj < 4; nj++) {
            uint32_t t[4];
            ldsm_x4(sb + SLB + boffL + nj * (16 * 32), t);
            b[2 * nj][0] = t[0]; b[2 * nj][1] = t[1];
            b[2 * nj + 1][0] = t[2]; b[2 * nj + 1][1] = t[3];
        }
#pragma unroll
        for (int mi = 0; mi < 2; mi++)
#pragma unroll
            for (int ni = 0; ni < 8; ni++)
                mma_f16(tac[mi][ni], ah[mi], b[ni]);
    }

    // ---- store ----
    {
        const int r  = lane >> 2;
        const int c2 = (lane & 3) * 2;
#pragma unroll
        for (int mi = 0; mi < 2; mi++) {
#pragma unroll
            for (int ni = 0; ni < 8; ni++) {
                const int m = m0 + wm + mi * 16 + r;
                const int n = n0 + ni * 8 + c2;
                float* p = out + (size_t)m * N_DIM + n;
                *reinterpret_cast<float2*>(p) =
                    make_float2(tac[mi][ni][0], tac[mi][ni][1]);
                *reinterpret_cast<float2*>(p + 8 * (size_t)N_DIM) =
                    make_float2(tac[mi][ni][2], tac[mi][ni][3]);
            }
        }
    }
}

// ---------------------------------------------------------------------------
// kernel_launch — inputs: x, qweight, scales, zeros, lora_A, lora_B
// ---------------------------------------------------------------------------
extern "C" void kernel_launch(void* const* d_in, const int* in_sizes, int n_in,
                              void* d_out, int out_size) {
    const float* x      = (const float*)d_in[0];
    const int*   qw     = (const int*)  d_in[1];
    const float* scales = (const float*)d_in[2];
    const int*   zeros  = (const int*)  d_in[3];
    const float* loraA  = (const float*)d_in[4];
    const float* loraB  = (const float*)d_in[5];
    float*       out    = (float*)d_out;

    cudaFuncSetAttribute(gptq_lora_mma,
                         cudaFuncAttributeMaxDynamicSharedMemorySize, SMEM_BYTES);

    x16_kernel<<<(int)(((size_t)M_DIM * K_DIM) / (256 * 8)), 256>>>(x);
    pack_w16<<<(int)(((size_t)N_DIM * K_DIM) / (256 * 8)), 256>>>(qw, zeros, scales);
    lora_xa_kernel<<<M_DIM, 256>>>(x, loraA);

    dim3 grid(M_DIM / BM, N_DIM / BN);   // (4, 172): m fastest -> w16 L2 dedup
    gptq_lora_mma<<<grid, 64, SMEM_BYTES>>>(loraB, out);
}

// round 13
// speedup vs baseline: 1.3848x; 1.3848x over previous
#include <cuda_runtime.h>
#include <cuda_fp16.h>
#include <cstdint>

// ---------------------------------------------------------------------------
// Problem constants
// ---------------------------------------------------------------------------
#define M_DIM 256
#define K_DIM 4096
#define N_DIM 11008
#define G_DIM 32
#define R_DIM 16
#define SCALING 2.0f

#define BM 64
#define BN 64
#define BK 32
#define KT (K_DIM / BK)     // 128

// SMEM: 4 stages. A [64][32] fp16 pitch 80 (5120 B), B [64][32] fp16 pitch 80.
#define PITCH  80
#define A_ST   5120
#define NSTG   4
#define B_BASE (NSTG * A_ST)              // 20480
#define B_ST   5120
#define SMEM_BYTES (B_BASE + NSTG * B_ST) // 40960  -> 5 CTAs/SM
// LoRA tiles reuse stage-0 smem after the main loop:
#define SXA 0        // xa [64][16] fp16, pitch 32
#define SLB 2048     // lB [64][16] fp16, pitch 32

// Global scratch
__device__ __align__(16) float  g_xa[M_DIM * R_DIM];
__device__ __align__(16) __half g_x16[(size_t)M_DIM * K_DIM];   // x in fp16
__device__ __align__(16) __half g_w16[(size_t)N_DIM * K_DIM];   // (q-z)*s in fp16

// ---------------------------------------------------------------------------
// helpers (family-common PTX)
// ---------------------------------------------------------------------------
__device__ __forceinline__ uint32_t smem_u32(const void* p) {
    uint32_t a;
    asm("{ .reg .u64 t; cvta.to.shared.u64 t, %1; cvt.u32.u64 %0, t; }"
        : "=r"(a) : "l"(p));
    return a;
}
__device__ __forceinline__ void ldsm_x4(uint32_t addr, uint32_t* r) {
    asm volatile("ldmatrix.sync.aligned.m8n8.x4.shared.b16 {%0,%1,%2,%3}, [%4];"
                 : "=r"(r[0]), "=r"(r[1]), "=r"(r[2]), "=r"(r[3]) : "r"(addr));
}
__device__ __forceinline__ void ldsm_x2(uint32_t addr, uint32_t* r) {
    asm volatile("ldmatrix.sync.aligned.m8n8.x2.shared.b16 {%0,%1}, [%2];"
                 : "=r"(r[0]), "=r"(r[1]) : "r"(addr));
}
__device__ __forceinline__ void mma_f16(float* c, const uint32_t* a, const uint32_t* b) {
    asm volatile(
        "mma.sync.aligned.m16n8k16.row.col.f32.f16.f16.f32 "
        "{%0,%1,%2,%3}, {%4,%5,%6,%7}, {%8,%9}, {%0,%1,%2,%3};"
        : "+f"(c[0]), "+f"(c[1]), "+f"(c[2]), "+f"(c[3])
        : "r"(a[0]), "r"(a[1]), "r"(a[2]), "r"(a[3]), "r"(b[0]), "r"(b[1]));
}
__device__ __forceinline__ void cpa16(uint32_t dst, const void* src) {
    asm volatile("cp.async.cg.shared.global [%0], [%1], 16;"
                 :: "r"(dst), "l"(src) : "memory");
}
__device__ __forceinline__ void cpa_commit() {
    asm volatile("cp.async.commit_group;" ::: "memory");
}
__device__ __forceinline__ void cpa_wait2() {
    asm volatile("cp.async.wait_group 2;" ::: "memory");
}
__device__ __forceinline__ uint32_t pack_f16(float v0, float v1) {
    __half2 p = __floats2half2_rn(v0, v1);
    return *reinterpret_cast<uint32_t*>(&p);
}

// ---------------------------------------------------------------------------
// Kernel 0: fused x-prep. One block per m-row (256 blocks x 256 threads):
//   - writes g_x16[m, :] (fp16 conversion)
//   - reduces xa[m, r] = SCALING * sum_k x[m,k] * lora_A[r,k]
// ---------------------------------------------------------------------------
__global__ __launch_bounds__(256)
void xprep_kernel(const float* __restrict__ x, const float* __restrict__ loraA) {
    const int m   = blockIdx.x;
    const int tid = threadIdx.x;
    const int lid = tid & 31;
    const int wid = tid >> 5;

    float acc[R_DIM];
#pragma unroll
    for (int r = 0; r < R_DIM; r++) acc[r] = 0.f;

    const float4* x4 = reinterpret_cast<const float4*>(x + (size_t)m * K_DIM);
    const float4* a4 = reinterpret_cast<const float4*>(loraA);
    uint2* xo = reinterpret_cast<uint2*>(g_x16 + (size_t)m * K_DIM);

#pragma unroll
    for (int i = 0; i < 4; i++) {
        const int f = tid + i * 256;           // float4 index within row
        float4 xv = x4[f];
        // fp16 conversion write
        xo[f] = make_uint2(pack_f16(xv.x, xv.y), pack_f16(xv.z, xv.w));
        // lora_A reduction
#pragma unroll
        for (int r = 0; r < R_DIM; r++) {
            float4 av = a4[r * (K_DIM / 4) + f];
            acc[r] = fmaf(xv.x, av.x, acc[r]);
            acc[r] = fmaf(xv.y, av.y, acc[r]);
            acc[r] = fmaf(xv.z, av.z, acc[r]);
            acc[r] = fmaf(xv.w, av.w, acc[r]);
        }
    }
#pragma unroll
    for (int r = 0; r < R_DIM; r++) {
#pragma unroll
        for (int o = 16; o > 0; o >>= 1)
            acc[r] += __shfl_xor_sync(0xFFFFFFFFu, acc[r], o);
    }
    __shared__ float red[8][R_DIM];
    if (lid == 0) {
#pragma unroll
        for (int r = 0; r < R_DIM; r++) red[wid][r] = acc[r];
    }
    __syncthreads();
    if (tid < R_DIM) {
        float v = 0.f;
#pragma unroll
        for (int w = 0; w < 8; w++) v += red[w][tid];
        g_xa[m * R_DIM + tid] = v * SCALING;
    }
}

// ---------------------------------------------------------------------------
// Kernel 0b: w16 = (qweight - zeros) * scales in fp16 (scale folded in).
// 16 elements/thread (never crosses a 128-elem group boundary).
// ---------------------------------------------------------------------------
__global__ __launch_bounds__(256)
void pack_w16(const int* __restrict__ qw, const int* __restrict__ zeros,
              const float* __restrict__ scales) {
    const size_t base = ((size_t)blockIdx.x * 256 + threadIdx.x) * 16;
    const int o = (int)(base >> 12);
    const int i = (int)(base & 4095);
    const int g = o * G_DIM + (i >> 7);
    const float z = (float)zeros[g];
    const float s = scales[g];
    const float nz = -z * s;

    int4 a = reinterpret_cast<const int4*>(qw + base)[0];
    int4 b = reinterpret_cast<const int4*>(qw + base)[1];
    int4 c = reinterpret_cast<const int4*>(qw + base)[2];
    int4 d = reinterpret_cast<const int4*>(qw + base)[3];

    uint4 w0, w1;
    w0.x = pack_f16(fmaf((float)a.x, s, nz), fmaf((float)a.y, s, nz));
    w0.y = pack_f16(fmaf((float)a.z, s, nz), fmaf((float)a.w, s, nz));
    w0.z = pack_f16(fmaf((float)b.x, s, nz), fmaf((float)b.y, s, nz));
    w0.w = pack_f16(fmaf((float)b.z, s, nz), fmaf((float)b.w, s, nz));
    w1.x = pack_f16(fmaf((float)c.x, s, nz), fmaf((float)c.y, s, nz));
    w1.y = pack_f16(fmaf((float)c.z, s, nz), fmaf((float)c.w, s, nz));
    w1.z = pack_f16(fmaf((float)d.x, s, nz), fmaf((float)d.y, s, nz));
    w1.w = pack_f16(fmaf((float)d.z, s, nz), fmaf((float)d.w, s, nz));

    reinterpret_cast<uint4*>(g_w16 + base)[0] = w0;
    reinterpret_cast<uint4*>(g_w16 + base)[1] = w1;
}

// ---------------------------------------------------------------------------
// Kernel 2: main GEMM — exact R10 configuration (validated 120.6us).
// CTA 64x64, 128 threads, 4 warps (2m x 2n, 32x32 each), BK=32,
// 4-stage cp.async ring, distance-3 prefetch, 5 CTAs/SM.
// Scales pre-folded; tac accumulates f32 directly; LoRA k16 epilogue.
// ---------------------------------------------------------------------------
__global__ __launch_bounds__(128, 5)
void gptq_lora_mma(const float* __restrict__ loraB,
                   float*       __restrict__ out) {
    extern __shared__ __align__(16) char sm[];
    const uint32_t sb = smem_u32(sm);

    const int tid  = threadIdx.x;
    const int lane = tid & 31;
    const int wid  = tid >> 5;
    const int m0   = blockIdx.x * BM;    // 4 m-tiles (fastest -> w16 L2 dedup)
    const int n0   = blockIdx.y * BN;    // 172 n-tiles

    // ---- loader mappings: 64 rows x 64B per tile; 2 threads/row, 32B each ----
    const int lrow = tid >> 1;
    const int lhal = (tid & 1) * 32;                 // byte offset in row
    const __half* ag = g_x16 + (size_t)(m0 + lrow) * K_DIM + (lhal >> 1);
    const __half* bg = g_w16 + (size_t)(n0 + lrow) * K_DIM + (lhal >> 1);
    const uint32_t l_soff = (uint32_t)(lrow * PITCH + lhal);

    // ---- prologue: stages 0..2 ----
#pragma unroll
    for (int s = 0; s < 3; s++) {
        const uint32_t As = sb + s * A_ST;
        const uint32_t Bs = sb + B_BASE + s * B_ST;
        cpa16(As + l_soff,      ag + s * BK);
        cpa16(As + l_soff + 16, ag + s * BK + 8);
        cpa16(Bs + l_soff,      bg + s * BK);
        cpa16(Bs + l_soff + 16, bg + s * BK + 8);
        cpa_commit();
    }

    // ---- accumulators / compute mappings ----
    float tac[2][4][4];
#pragma unroll
    for (int mi = 0; mi < 2; mi++)
#pragma unroll
        for (int ni = 0; ni < 4; ni++)
#pragma unroll
            for (int j = 0; j < 4; j++) tac[mi][ni][j] = 0.f;

    const int wm = (wid >> 1) * 32;            // 0/32
    const int wn = (wid & 1) * 32;             // 0/32
    const uint32_t aoff  = (uint32_t)((wm + (lane & 15)) * PITCH + ((lane >> 4) << 4));
    const uint32_t boff4 = (uint32_t)((wn + (lane & 7) + ((lane >> 4) << 3)) * PITCH
                                      + (((lane >> 3) & 1) << 4));

    cpa_wait2();          // stage 0 complete (own groups)
    __syncthreads();      // all threads' -> fully visible

    // frag double buffers
    uint32_t fa[2][2][4], fb[2][4][2];

    for (int kt = 0; kt < KT; kt++) {
        // 1. prefetch stage kt+3
        if (kt < KT - 3) {
            const int ks = kt + 3;
            const int st = ks & 3;
            const uint32_t As = sb + st * A_ST;
            const uint32_t Bs = sb + B_BASE + st * B_ST;
            cpa16(As + l_soff,      ag + ks * BK);
            cpa16(As + l_soff + 16, ag + ks * BK + 8);
            cpa16(Bs + l_soff,      bg + ks * BK);
            cpa16(Bs + l_soff + 16, bg + ks * BK + 8);
        }
        cpa_commit();

        // 2. compute stage kt&3: 2 x k16 HMMA, frag-double-buffered
        {
            const uint32_t Ab = sb + (uint32_t)((kt & 3) * A_ST) + aoff;
            const uint32_t Bb = sb + B_BASE + (uint32_t)((kt & 3) * B_ST) + boff4;

            // load kk=0 into buffer 0
#pragma unroll
            for (int mi = 0; mi < 2; mi++)
                ldsm_x4(Ab + mi * (16 * PITCH), fa[0][mi]);
#pragma unroll
            for (int nj = 0; nj < 2; nj++) {
                uint32_t t[4];
                ldsm_x4(Bb + nj * (16 * PITCH), t);
                fb[0][2 * nj][0] = t[0]; fb[0][2 * nj][1] = t[1];
                fb[0][2 * nj + 1][0] = t[2]; fb[0][2 * nj + 1][1] = t[3];
            }
#pragma unroll
            for (int kk = 0; kk < 2; kk++) {
                const int cur = kk & 1, nxt = cur ^ 1;
                if (kk < 1) {
                    const uint32_t kb = 32;   // second k16 half (16 fp16 = 32B)
#pragma unroll
                    for (int mi = 0; mi < 2; mi++)
                        ldsm_x4(Ab + mi * (16 * PITCH) + kb, fa[nxt][mi]);
#pragma unroll
                    for (int nj = 0; nj < 2; nj++) {
                        uint32_t t[4];
                        ldsm_x4(Bb + nj * (16 * PITCH) + kb, t);
                        fb[nxt][2 * nj][0] = t[0]; fb[nxt][2 * nj][1] = t[1];
                        fb[nxt][2 * nj + 1][0] = t[2]; fb[nxt][2 * nj + 1][1] = t[3];
                    }
                }
#pragma unroll
                for (int mi = 0; mi < 2; mi++)
#pragma unroll
                    for (int ni = 0; ni < 4; ni++)
                        mma_f16(tac[mi][ni], fa[cur][mi], fb[cur][ni]);
            }
        }

        // 3. stage kt+1 complete; publish
        cpa_wait2();
        __syncthreads();
    }

    // ---- LoRA tiles: reuse stage-0 smem (all compute done) ----
    {
        const int row = tid & 63;
        const float* src = (tid < 64)
            ? (g_xa + (size_t)(m0 + row) * R_DIM)
            : (loraB + (size_t)(n0 + row) * R_DIM);
        char* dst = sm + ((tid < 64) ? SXA : SLB) + row * 32;
        float4 v0 = reinterpret_cast<const float4*>(src)[0];
        float4 v1 = reinterpret_cast<const float4*>(src)[1];
        float4 v2 = reinterpret_cast<const float4*>(src)[2];
        float4 v3 = reinterpret_cast<const float4*>(src)[3];
        *reinterpret_cast<uint4*>(dst) =
            make_uint4(pack_f16(v0.x, v0.y), pack_f16(v0.z, v0.w),
                       pack_f16(v1.x, v1.y), pack_f16(v1.z, v1.w));
        *reinterpret_cast<uint4*>(dst + 16) =
            make_uint4(pack_f16(v2.x, v2.y), pack_f16(v2.z, v2.w),
                       pack_f16(v3.x, v3.y), pack_f16(v3.z, v3.w));
    }
    __syncthreads();

    // ---- LoRA k16 step ----
    {
        uint32_t ah[2][4], b[4][2];
#pragma unroll
        for (int mi = 0; mi < 2; mi++)
            ldsm_x4(sb + SXA + (uint32_t)((wm + mi * 16 + (lane & 15)) * 32
                                          + ((lane >> 4) << 4)), ah[mi]);
#pragma unroll
        for (int ni = 0; ni < 4; ni++)
            ldsm_x2(sb + SLB + (uint32_t)((wn + ni * 8 + (lane & 7)) * 32
                                          + (((lane >> 3) & 1) << 4)), b[ni]);
#pragma unroll
        for (int mi = 0; mi < 2; mi++)
#pragma unroll
            for (int ni = 0; ni < 4; ni++)
                mma_f16(tac[mi][ni], ah[mi], b[ni]);
    }

    // ---- store ----
    {
        const int r  = lane >> 2;
        const int c2 = (lane & 3) * 2;
#pragma unroll
        for (int mi = 0; mi < 2; mi++) {
#pragma unroll
            for (int ni = 0; ni < 4; ni++) {
                const int m = m0 + wm + mi * 16 + r;
                const int n = n0 + wn + ni * 8 + c2;
                float* p = out + (size_t)m * N_DIM + n;
                *reinterpret_cast<float2*>(p) =
                    make_float2(tac[mi][ni][0], tac[mi][ni][1]);
                *reinterpret_cast<float2*>(p + 8 * (size_t)N_DIM) =
                    make_float2(tac[mi][ni][2], tac[mi][ni][3]);
            }
        }
    }
}

// ---------------------------------------------------------------------------
// kernel_launch — inputs: x, qweight, scales, zeros, lora_A, lora_B
// ---------------------------------------------------------------------------
extern "C" void kernel_launch(void* const* d_in, const int* in_sizes, int n_in,
                              void* d_out, int out_size) {
    const float* x      = (const float*)d_in[0];
    const int*   qw     = (const int*)  d_in[1];
    const float* scales = (const float*)d_in[2];
    const int*   zeros  = (const int*)  d_in[3];
    const float* loraA  = (const float*)d_in[4];
    const float* loraB  = (const float*)d_in[5];
    float*       out    = (float*)d_out;

    cudaFuncSetAttribute(gptq_lora_mma,
                         cudaFuncAttributeMaxDynamicSharedMemorySize, SMEM_BYTES);

    xprep_kernel<<<M_DIM, 256>>>(x, loraA);
    pack_w16<<<(int)(((size_t)N_DIM * K_DIM) / (256 * 16)), 256>>>(qw, zeros, scales);

    dim3 grid(M_DIM / BM, N_DIM / BN);   // (4, 172): m fastest -> w16 L2 dedup
    gptq_lora_mma<<<grid, 128, SMEM_BYTES>>>(loraB, out);
}